// round 10
// baseline (speedup 1.0000x reference)
#include <cuda_runtime.h>

// BiasedFeatureDropout: out = x * 1.25 * (threefry_bits(i) < T(channel))
// Bit-exact JAX partitionable threefry-2x32, keys (0,1), counter hi=0.
//
// Round-10 build: pipe-BALANCED mix. Model (fits all 8 prior benches):
// both int pipes issue 0.5 warp-instr/cyc/SMSP; IMAD.WIDE = 2 fma slots.
// R9 was alu-bound (46 alu vs 25.5 fma slots). Convert exactly 7 SHF
// rounds to wide-mul rotates: alu ~40, fma ~38 slots -> balanced.
// Wide round = one asm block (mul.wide + pair-split mov.b64 + LOP3 0x56)
// so no u64-shift instruction bloat. Bounds guard dropped (grid exact).

static constexpr unsigned KS2      = 0x1BD11BDBu;   // 0 ^ 1 ^ 0x1BD11BDA
static constexpr unsigned HW       = 56u * 56u;     // 3136, divisible by 8
static constexpr unsigned THR_BIAS = 858993664u;    // keep=0.2f
static constexpr unsigned THR_REG  = 3435974144u;   // keep=0.8f

// SHF round: add + funnel-shift rotate + xor           (alu 2, fma 1)
#define RS(rr)      { x0 += x1; x1 = __funnelshift_l(x1, x1, (rr)) ^ x0; }
// SHF round with folded x0 key-injection (IADD3 3-in)  (alu 3)
#define RSF(rr, a)  { x0 += x1 + (a); x1 = __funnelshift_l(x1, x1, (rr)) ^ x0; }
// PRMT round: rot16 sel=0x1032, rot24 sel=0x0321       (alu 2, fma 1)
#define RP(sel)     { x0 += x1; x1 = __byte_perm(x1, 0u, (sel)) ^ x0; }
// WIDE round: rot(x,r)=lo|hi of x*(1<<r); LOP3 0x56 = (a|b)^c
//                                                      (alu 1, fma 1+2slots)
#define RW(pp)      { x0 += x1;                                          \
    unsigned nx_;                                                        \
    asm("{\n\t"                                                          \
        ".reg .b64 t_; .reg .b32 lo_, hi_;\n\t"                          \
        "mul.wide.u32 t_, %1, %2;\n\t"                                   \
        "mov.b64 {lo_, hi_}, t_;\n\t"                                    \
        "lop3.b32 %0, lo_, hi_, %3, 0x56;\n\t"                           \
        "}" : "=r"(nx_) : "r"(x1), "r"(pp), "r"(x0));                    \
    x1 = nx_; }

__device__ __forceinline__ unsigned threefry_bits(unsigned ctr,
                                                  unsigned p6, unsigned p15,
                                                  unsigned p29) {
    unsigned x0, x1;
    x1 = ctr + 1u;                               // x1 = ctr + ks1(=1)
    // r1 (rot13): x0 = 0 + x1 (free), x1 = rot13(x1) ^ x0
    x0 = x1;
    x1 = __funnelshift_l(x1, x1, 13) ^ x0;
    RW(p15)                                      // r2   wide
    RS(26)                                       // r3
    RW(p6)                                       // r4   wide
    x1 += KS2 + 1u;                              // inj1: x1 += ks2+1
    RSF(17, 1u)                                  // r5   (x0 += ks1=1 folded)
    RW(p29)                                      // r6   wide
    RP(0x1032u)                                  // r7   rot16
    RP(0x0321u)                                  // r8   rot24
    x1 += 2u;                                    // inj2: x1 += ks0+2
    RSF(13, KS2)                                 // r9   (x0 += ks2 folded)
    RW(p15)                                      // r10  wide
    RS(26)                                       // r11
    RW(p6)                                       // r12  wide
    x1 += 4u;                                    // inj3: x1 += ks1+3
    RS(17)                                       // r13  (x0 += ks0=0, free)
    RW(p29)                                      // r14  wide
    RP(0x1032u)                                  // r15  rot16
    RP(0x0321u)                                  // r16  rot24
    x1 += KS2 + 4u;                              // inj4: x1 += ks2+4
    RSF(13, 1u)                                  // r17  (x0 += ks1=1 folded)
    RW(p15)                                      // r18  wide
    RS(26)                                       // r19
    RS(6)                                        // r20
    // final: (x0 + ks2) ^ (x1 + ks0 + 5)
    return (x0 + KS2) ^ (x1 + 5u);
}

__global__ __launch_bounds__(256, 4)
void biased_dropout_kernel(const float4* __restrict__ x,
                           float4* __restrict__ y,
                           unsigned one) {          // always 1, opaque to ptxas
    unsigned t = blockIdx.x * blockDim.x + threadIdx.x;   // grid covers n exactly

    unsigned base = t * 8u;
    unsigned ch  = (base / HW) & 255u;               // HW % 8 == 0
    unsigned thr = (ch < 32u) ? THR_BIAS : THR_REG;

    unsigned p6 = one << 6, p15 = one << 15, p29 = one << 29;

    float4 v0 = x[2u * t];
    float4 v1 = x[2u * t + 1u];

    unsigned b[8];
#pragma unroll
    for (int i = 0; i < 8; i++)
        b[i] = threefry_bits(base + (unsigned)i, p6, p15, p29);

    float4 o0, o1;
    o0.x = (b[0] < thr) ? v0.x * 1.25f : 0.0f;
    o0.y = (b[1] < thr) ? v0.y * 1.25f : 0.0f;
    o0.z = (b[2] < thr) ? v0.z * 1.25f : 0.0f;
    o0.w = (b[3] < thr) ? v0.w * 1.25f : 0.0f;
    o1.x = (b[4] < thr) ? v1.x * 1.25f : 0.0f;
    o1.y = (b[5] < thr) ? v1.y * 1.25f : 0.0f;
    o1.z = (b[6] < thr) ? v1.z * 1.25f : 0.0f;
    o1.w = (b[7] < thr) ? v1.w * 1.25f : 0.0f;

    y[2u * t]      = o0;
    y[2u * t + 1u] = o1;
}

extern "C" void kernel_launch(void* const* d_in, const int* in_sizes, int n_in,
                              void* d_out, int out_size) {
    (void)n_in; (void)out_size;
    const float4* x = (const float4*)d_in[0];
    float4* y = (float4*)d_out;
    unsigned n = (unsigned)in_sizes[0];          // 51,380,224
    unsigned n_thr = n / 8u;                     // 6,422,528 (exact)
    unsigned blocks = n_thr / 256u;              // 25,088 (exact, no remainder)
    biased_dropout_kernel<<<blocks, 256>>>(x, y, 1u);
}

// round 11
// speedup vs baseline: 1.0025x; 1.0025x over previous
#include <cuda_runtime.h>

// BiasedFeatureDropout: out = x * 1.25 * (threefry_bits(i) < T(channel))
// Bit-exact JAX partitionable threefry-2x32, keys (0,1), counter hi=0.
//
// Round-11 build: R9 (best, 139.3us) with 4 SHF rounds converted to plain
// C++ wide-mul rotates (IMAD.WIDE + LOP3, no asm -> no forced MOV bloat).
// Model: dur = instrs/elem / min(0.76 issue cap, pipe caps). R9 was at
// alu share 0.648 (~binding). This drops alu share to ~0.59 so only the
// 0.76 issue cap binds, at constant total instruction count.

static constexpr unsigned KS2      = 0x1BD11BDBu;   // 0 ^ 1 ^ 0x1BD11BDA
static constexpr unsigned HW       = 56u * 56u;     // 3136, divisible by 8
static constexpr unsigned THR_BIAS = 858993664u;    // keep=0.2f
static constexpr unsigned THR_REG  = 3435974144u;   // keep=0.8f

// SHF round: add + funnel-shift rotate + xor            (3 instr: 1 fma/2 alu)
#define RS(rr)      { x0 += x1; x1 = __funnelshift_l(x1, x1, (rr)) ^ x0; }
// SHF round with folded x0 key-injection (3-input add)
#define RSF(rr, a)  { x0 += x1 + (a); x1 = __funnelshift_l(x1, x1, (rr)) ^ x0; }
// PRMT round: rot16 sel=0x1032, rot24 sel=0x0321
#define RP(sel)     { x0 += x1; x1 = __byte_perm(x1, 0u, (sel)) ^ x0; }
// WIDE round (plain C++): rot(x,r) = lo|hi of x*(1<<r); ptxas emits
// IMAD.WIDE + LOP3 (lo|hi)^x0 with a natural register pair (no MOVs).
#define RSW(pp)     { x0 += x1;                                          \
                      unsigned long long t_ = (unsigned long long)x1 * (pp); \
                      x1 = ((unsigned)t_ | (unsigned)(t_ >> 32)) ^ x0; }

__device__ __forceinline__ unsigned threefry_bits(unsigned ctr,
                                                  unsigned p15, unsigned p29) {
    unsigned x0, x1;
    x1 = ctr + 1u;                               // x1 = ctr + ks1(=1)
    // r1 (rot13): x0 = 0 + x1 (register alias, no work), x1 = rot13(x1)^x0
    x0 = x1;
    x1 = __funnelshift_l(x1, x1, 13) ^ x0;
    RSW(p15)                                     // r2   wide
    RS(26) RS(6)                                 // r3-r4
    x1 += KS2 + 1u;                              // inj1: x1 += ks2+1
    RSF(17, 1u)                                  // r5  (x0 += ks1=1 folded)
    RSW(p29)                                     // r6   wide
    RP(0x1032u)                                  // r7  rot16
    RP(0x0321u)                                  // r8  rot24
    x1 += 2u;                                    // inj2: x1 += ks0+2
    RSF(13, KS2)                                 // r9  (x0 += ks2 folded)
    RSW(p15)                                     // r10  wide
    RS(26) RS(6)                                 // r11-r12
    x1 += 4u;                                    // inj3: x1 += ks1+3
    RS(17)                                       // r13 (x0 += ks0=0, free)
    RSW(p29)                                     // r14  wide
    RP(0x1032u)                                  // r15 rot16
    RP(0x0321u)                                  // r16 rot24
    x1 += KS2 + 4u;                              // inj4: x1 += ks2+4
    RSF(13, 1u)                                  // r17 (x0 += ks1=1 folded)
    RS(15) RS(26) RS(6)                          // r18-r20
    // final: (x0 + ks2) ^ (x1 + ks0 + 5)
    return (x0 + KS2) ^ (x1 + 5u);
}

__global__ __launch_bounds__(256, 4)
void biased_dropout_kernel(const float4* __restrict__ x,
                           float4* __restrict__ y,
                           unsigned one) {          // always 1, opaque to ptxas
    unsigned t = blockIdx.x * blockDim.x + threadIdx.x;   // grid covers n exactly

    unsigned base = t * 8u;
    unsigned ch  = (base / HW) & 255u;               // HW % 8 == 0
    unsigned thr = (ch < 32u) ? THR_BIAS : THR_REG;

    unsigned p15 = one << 15, p29 = one << 29;       // runtime-opaque pow2s

    float4 v0 = x[2u * t];
    float4 v1 = x[2u * t + 1u];

    unsigned b[8];
#pragma unroll
    for (int i = 0; i < 8; i++)
        b[i] = threefry_bits(base + (unsigned)i, p15, p29);

    float4 o0, o1;
    o0.x = (b[0] < thr) ? v0.x * 1.25f : 0.0f;
    o0.y = (b[1] < thr) ? v0.y * 1.25f : 0.0f;
    o0.z = (b[2] < thr) ? v0.z * 1.25f : 0.0f;
    o0.w = (b[3] < thr) ? v0.w * 1.25f : 0.0f;
    o1.x = (b[4] < thr) ? v1.x * 1.25f : 0.0f;
    o1.y = (b[5] < thr) ? v1.y * 1.25f : 0.0f;
    o1.z = (b[6] < thr) ? v1.z * 1.25f : 0.0f;
    o1.w = (b[7] < thr) ? v1.w * 1.25f : 0.0f;

    y[2u * t]      = o0;
    y[2u * t + 1u] = o1;
}

extern "C" void kernel_launch(void* const* d_in, const int* in_sizes, int n_in,
                              void* d_out, int out_size) {
    (void)n_in; (void)out_size;
    const float4* x = (const float4*)d_in[0];
    float4* y = (float4*)d_out;
    unsigned n = (unsigned)in_sizes[0];          // 51,380,224
    unsigned n_thr = n / 8u;                     // 6,422,528 (exact)
    unsigned blocks = n_thr / 256u;              // 25,088 (exact, no remainder)
    biased_dropout_kernel<<<blocks, 256>>>(x, y, 1u);
}

// round 12
// speedup vs baseline: 1.0538x; 1.0512x over previous
#include <cuda_runtime.h>

// BiasedFeatureDropout: out = x * 1.25 * (threefry_bits(i) < T(channel))
// Bit-exact JAX partitionable threefry-2x32, keys (0,1), counter hi=0.
//
// Round-12 build: R9 (best, 139.3us) with EVERY add steered to the fma
// pipe as IMAD (opaque 'one'), including the 3 folded x0-injections
// (split into 2 IMADs each) and init/final adds. No IMAD.WIDE anywhere
// (R10/R11 showed wide ops cost occupancy + latency).
// Model: alu slots 46 -> 43 (binding pipe, 2 cyc/slot), fma 25 -> 31
// (headroom), issue share alu 0.648 -> 0.573 -> issue can rise past 0.76.

static constexpr unsigned KS2      = 0x1BD11BDBu;   // 0 ^ 1 ^ 0x1BD11BDA
static constexpr unsigned HW       = 56u * 56u;     // 3136, divisible by 8
static constexpr unsigned THR_BIAS = 858993664u;    // keep=0.2f
static constexpr unsigned THR_REG  = 3435974144u;   // keep=0.8f

// a*one + c -> IMAD (fma pipe); 'one' is a runtime kernel arg (==1)
__device__ __forceinline__ unsigned madd(unsigned a, unsigned one, unsigned c) {
    unsigned r;
    asm("mad.lo.u32 %0, %1, %2, %3;" : "=r"(r) : "r"(a), "r"(one), "r"(c));
    return r;
}

// SHF round: IMAD add (fma) + SHF rotate (alu) + LOP3 xor (alu)
#define RS(rr)      { x0 = madd(x1, one, x0);                      \
                      x1 = __funnelshift_l(x1, x1, (rr)) ^ x0; }
// SHF round with x0 key-injection: two IMADs (fma) instead of one IADD3 (alu)
#define RSJ(rr, a)  { x0 = madd(x1, one, x0); x0 = madd(x0, one, (a)); \
                      x1 = __funnelshift_l(x1, x1, (rr)) ^ x0; }
// PRMT round: rot16 sel=0x1032, rot24 sel=0x0321
#define RP(sel)     { x0 = madd(x1, one, x0);                      \
                      x1 = __byte_perm(x1, 0u, (sel)) ^ x0; }

__device__ __forceinline__ unsigned threefry_bits(unsigned base, unsigned i,
                                                  unsigned one) {
    unsigned x0, x1;
    x1 = madd(base, one, i + 1u);                // x1 = ctr + ks1(=1)
    // r1 (rot13): x0 = 0 + x1 (register alias), x1 = rot13(x1) ^ x0
    x0 = x1;
    x1 = __funnelshift_l(x1, x1, 13) ^ x0;
    RS(15) RS(26) RS(6)                          // r2-r4
    x1 = madd(x1, one, KS2 + 1u);                // inj1: x1 += ks2+1
    RSJ(17, 1u)                                  // r5  (x0 += ks1=1, IMAD)
    RS(29)                                       // r6
    RP(0x1032u)                                  // r7  rot16
    RP(0x0321u)                                  // r8  rot24
    x1 = madd(x1, one, 2u);                      // inj2: x1 += ks0+2
    RSJ(13, KS2)                                 // r9  (x0 += ks2, IMAD)
    RS(15) RS(26) RS(6)                          // r10-r12
    x1 = madd(x1, one, 4u);                      // inj3: x1 += ks1+3
    RS(17)                                       // r13 (x0 += ks0=0, free)
    RS(29)                                       // r14
    RP(0x1032u)                                  // r15 rot16
    RP(0x0321u)                                  // r16 rot24
    x1 = madd(x1, one, KS2 + 4u);                // inj4: x1 += ks2+4
    RSJ(13, 1u)                                  // r17 (x0 += ks1=1, IMAD)
    RS(15) RS(26) RS(6)                          // r18-r20
    // final: (x0 + ks2) ^ (x1 + ks0 + 5) — both adds on IMAD
    return madd(x0, one, KS2) ^ madd(x1, one, 5u);
}

__global__ __launch_bounds__(256, 4)
void biased_dropout_kernel(const float4* __restrict__ x,
                           float4* __restrict__ y,
                           unsigned one) {          // always 1, opaque to ptxas
    unsigned t = blockIdx.x * blockDim.x + threadIdx.x;   // grid covers n exactly

    unsigned base = t * 8u;
    unsigned ch  = (base / HW) & 255u;               // HW % 8 == 0
    unsigned thr = (ch < 32u) ? THR_BIAS : THR_REG;

    float4 v0 = x[2u * t];
    float4 v1 = x[2u * t + 1u];

    unsigned b[8];
#pragma unroll
    for (int i = 0; i < 8; i++)
        b[i] = threefry_bits(base, (unsigned)i, one);

    float4 o0, o1;
    o0.x = (b[0] < thr) ? v0.x * 1.25f : 0.0f;
    o0.y = (b[1] < thr) ? v0.y * 1.25f : 0.0f;
    o0.z = (b[2] < thr) ? v0.z * 1.25f : 0.0f;
    o0.w = (b[3] < thr) ? v0.w * 1.25f : 0.0f;
    o1.x = (b[4] < thr) ? v1.x * 1.25f : 0.0f;
    o1.y = (b[5] < thr) ? v1.y * 1.25f : 0.0f;
    o1.z = (b[6] < thr) ? v1.z * 1.25f : 0.0f;
    o1.w = (b[7] < thr) ? v1.w * 1.25f : 0.0f;

    y[2u * t]      = o0;
    y[2u * t + 1u] = o1;
}

extern "C" void kernel_launch(void* const* d_in, const int* in_sizes, int n_in,
                              void* d_out, int out_size) {
    (void)n_in; (void)out_size;
    const float4* x = (const float4*)d_in[0];
    float4* y = (float4*)d_out;
    unsigned n = (unsigned)in_sizes[0];          // 51,380,224
    unsigned n_thr = n / 8u;                     // 6,422,528 (exact)
    unsigned blocks = n_thr / 256u;              // 25,088 (exact, no remainder)
    biased_dropout_kernel<<<blocks, 256>>>(x, y, 1u);
}